// round 13
// baseline (speedup 1.0000x reference)
#include <cuda_runtime.h>
#include <cuda_fp16.h>
#include <math.h>
#include <stdint.h>

#define NE    2048
#define FEAT  512
#define REST  8
#define HEAD  8
#define HL    512
#define NCOL  16384
#define OUTC  (HEAD*512)
#define BKH   64
#define PADH  72
#define ASTRH (128*PADH)
#define STG   3
#define SMEM_BYTES (2 * STG * ASTRH * 2)   // 110592 bytes

// ---------------- scratch ----------------------------------------------------
__device__ __half g_Y  [(size_t)2 * HEAD * NE * 512];
__device__ __half g_Yd [(size_t)HEAD * 512 * NE];
__device__ __half g_xt [(size_t)NCOL * FEAT];
__device__ __half g_W  [(size_t)3 * HL * FEAT];
__device__ __half g_S  [(size_t)HEAD * NE * NE];
__device__ float  g_ss [3 * NE];
__device__ float  g_rs [(size_t)HEAD * NE];

// ---------------- helpers ----------------------------------------------------
__device__ __forceinline__ uint32_t smem_u32(const void* p) {
    uint32_t a;
    asm("{ .reg .u64 t; cvta.to.shared.u64 t, %1; cvt.u32.u64 %0, t; }" : "=r"(a) : "l"(p));
    return a;
}
__device__ __forceinline__ void mma16(float* c, const uint32_t* a, const uint32_t* b) {
    asm volatile(
        "mma.sync.aligned.m16n8k16.row.col.f32.f16.f16.f32 "
        "{%0,%1,%2,%3}, {%4,%5,%6,%7}, {%8,%9}, {%0,%1,%2,%3};"
        : "+f"(c[0]), "+f"(c[1]), "+f"(c[2]), "+f"(c[3])
        : "r"(a[0]), "r"(a[1]), "r"(a[2]), "r"(a[3]), "r"(b[0]), "r"(b[1]));
}
__device__ __forceinline__ void ldsm4(uint32_t* r, uint32_t addr) {
    asm volatile("ldmatrix.sync.aligned.m8n8.x4.shared.b16 {%0,%1,%2,%3}, [%4];"
                 : "=r"(r[0]), "=r"(r[1]), "=r"(r[2]), "=r"(r[3]) : "r"(addr));
}
__device__ __forceinline__ void cp16(uint32_t dst, const void* src) {
    uint64_t g;
    asm("cvta.to.global.u64 %0, %1;" : "=l"(g) : "l"(src));
    asm volatile("cp.async.ca.shared.global [%0], [%1], 16;" :: "r"(dst), "l"(g));
}

__device__ __forceinline__ void ld_k(__half* S, const __half* gp, int ldk, int k0, int tid) {
#pragma unroll
    for (int i = 0; i < 8; i++) {
        int idx = tid + i * 128;
        int row = idx >> 3, ch = idx & 7;
        cp16(smem_u32(S + row * PADH + ch * 8), gp + (size_t)row * ldk + k0 + ch * 8);
    }
}

struct Acc { float a[4][8][4]; };

// ---------------- 3-stage, BK=64, fragment double-buffered mainloop ----------
__device__ __forceinline__ void gemm_main(Acc& F, const __half* A, const __half* B,
                                          int K, __half* sA, __half* sB) {
    const int tid = threadIdx.x;
    const int lane = tid & 31, wid = tid >> 5;
    const int wm = (wid & 1) * 64, wn = (wid >> 1) * 64;

    const int offA = (wm + (lane & 7) + ((lane >> 3) & 1) * 8) * PADH + ((lane >> 4) & 1) * 8;
    const int offB = (wn + (lane & 7) + ((lane >> 4) & 1) * 8) * PADH + ((lane >> 3) & 1) * 8;

    const uint32_t sA0 = smem_u32(sA), sB0 = smem_u32(sB);

#pragma unroll
    for (int mt = 0; mt < 4; mt++)
#pragma unroll
        for (int nt = 0; nt < 8; nt++)
#pragma unroll
            for (int j = 0; j < 4; j++) F.a[mt][nt][j] = 0.f;

#pragma unroll
    for (int s = 0; s < STG - 1; s++) {
        ld_k(sA + s * ASTRH, A, K, s * BKH, tid);
        ld_k(sB + s * ASTRH, B, K, s * BKH, tid);
        asm volatile("cp.async.commit_group;" ::: "memory");
    }

    const int KT = K / BKH;
    int ls = STG - 1;
    for (int kt = 0; kt < KT; kt++) {
        asm volatile("cp.async.wait_group %0;" :: "n"(STG - 2) : "memory");
        __syncthreads();
        if (kt + STG - 1 < KT) {
            ld_k(sA + ls * ASTRH, A, K, (kt + STG - 1) * BKH, tid);
            ld_k(sB + ls * ASTRH, B, K, (kt + STG - 1) * BKH, tid);
            ls = (ls + 1 == STG) ? 0 : ls + 1;
        }
        asm volatile("cp.async.commit_group;" ::: "memory");

        int buf = kt % STG;
        const uint32_t aB = sA0 + (buf * ASTRH + offA) * 2;
        const uint32_t bB = sB0 + (buf * ASTRH + offB) * 2;

        uint32_t af[2][4][4], bf[2][4][4];
#pragma unroll
        for (int mt = 0; mt < 4; mt++) ldsm4(af[0][mt], aB + (mt * 16 * PADH) * 2);
#pragma unroll
        for (int np = 0; np < 4; np++) ldsm4(bf[0][np], bB + (np * 16 * PADH) * 2);

#pragma unroll
        for (int ks = 0; ks < 4; ks++) {
            int cur = ks & 1, nxt = cur ^ 1;
            if (ks < 3) {
#pragma unroll
                for (int mt = 0; mt < 4; mt++)
                    ldsm4(af[nxt][mt], aB + (mt * 16 * PADH + 16 * (ks + 1)) * 2);
#pragma unroll
                for (int np = 0; np < 4; np++)
                    ldsm4(bf[nxt][np], bB + (np * 16 * PADH + 16 * (ks + 1)) * 2);
            }
#pragma unroll
            for (int mt = 0; mt < 4; mt++)
#pragma unroll
                for (int np = 0; np < 4; np++) {
                    mma16(F.a[mt][2 * np + 0], af[cur][mt], &bf[cur][np][0]);
                    mma16(F.a[mt][2 * np + 1], af[cur][mt], &bf[cur][np][2]);
                }
        }
    }
    __syncthreads();
}

// ---------------- fused prep: transpose x + round W + zero accumulators ------
__global__ __launch_bounds__(256) void prep_all(const float* __restrict__ x,
                                                const float* __restrict__ Wq,
                                                const float* __restrict__ Wk,
                                                const float* __restrict__ Wd) {
    int b = blockIdx.x;
    if (b < NE) {
        __shared__ float s[512 * 9];
        const int n = b, tid = threadIdx.x;
        const float* src = x + (size_t)n * 4096;
#pragma unroll
        for (int i = 0; i < 4; i++) {
            int v = (tid + i * 256) * 4;
            float4 t = *(const float4*)(src + v);
            int f = v >> 3, rr = v & 7;
            s[f * 9 + rr + 0] = t.x; s[f * 9 + rr + 1] = t.y;
            s[f * 9 + rr + 2] = t.z; s[f * 9 + rr + 3] = t.w;
        }
        __syncthreads();
#pragma unroll
        for (int rr = 0; rr < 8; rr++) {
            int f = threadIdx.x * 2;
            __half2 h = make_half2(__float2half_rn(s[f * 9 + rr]),
                                   __float2half_rn(s[(f + 1) * 9 + rr]));
            *(__half2*)(g_xt + ((size_t)n * 8 + rr) * 512 + f) = h;
        }
    } else if (b < NE + 768) {
        int bb = b - NE;
        int idx = (bb * 256 + threadIdx.x) * 4;
        int p = idx >> 18, off = idx & 262143;
        const float* W = (p == 0) ? Wq : (p == 1) ? Wk : Wd;
        float4 t = *(const float4*)(W + off);
        *(__half2*)(g_W + idx)     = make_half2(__float2half_rn(t.x), __float2half_rn(t.y));
        *(__half2*)(g_W + idx + 2) = make_half2(__float2half_rn(t.z), __float2half_rn(t.w));
        // fold accumulator zeroing into the first W blocks
        int i = bb * 256 + threadIdx.x;
        if (i < 3 * NE) g_ss[i] = 0.f;
        if (i < HEAD * NE) g_rs[i] = 0.f;
    }
}

// ---------------- projection GEMM + fused sum-of-squares --------------------
__global__ __launch_bounds__(128) void proj_tc() {
    extern __shared__ __half dsm[];
    __shared__ float csum[128];
    __half* sA = dsm;
    __half* sB = dsm + STG * ASTRH;
    const int p = blockIdx.z;
    const int m0 = blockIdx.y * 128, c0 = blockIdx.x * 128;

    const int tid = threadIdx.x, lane = tid & 31, wid = tid >> 5;
    const int g8 = lane >> 2, tg = lane & 3;
    const int wm = (wid & 1) * 64, wn = (wid >> 1) * 64;

    csum[tid] = 0.f;

    Acc F;
    gemm_main(F, g_W + (size_t)p * HL * FEAT + (size_t)m0 * FEAT,
              g_xt + (size_t)c0 * FEAT, FEAT, sA, sB);

    float sq[8];
#pragma unroll
    for (int nt = 0; nt < 8; nt++) sq[nt] = 0.f;

    if (p < 2) {
        __half* base = g_Y + (size_t)p * HEAD * NE * 512;
#pragma unroll
        for (int mt = 0; mt < 4; mt++)
#pragma unroll
            for (int half = 0; half < 2; half++) {
                int row = m0 + wm + mt * 16 + g8 + half * 8;
                int hh = row >> 6, l = row & 63;
#pragma unroll
                for (int nt = 0; nt < 8; nt++) {
                    int col = c0 + wn + nt * 8 + 2 * tg;
                    int n = col >> 3, r = col & 7;
                    __half h0 = __float2half_rn(F.a[mt][nt][half * 2 + 0]);
                    __half h1 = __float2half_rn(F.a[mt][nt][half * 2 + 1]);
                    float v0 = __half2float(h0), v1 = __half2float(h1);
                    *(__half2*)(base + ((size_t)hh * NE + n) * 512 + l * 8 + r) = make_half2(h0, h1);
                    sq[nt] += v0 * v0 + v1 * v1;
                }
            }
    } else {
        int mb = (c0 >> 3) + (wn >> 3);
#pragma unroll
        for (int mt = 0; mt < 4; mt++)
#pragma unroll
            for (int half = 0; half < 2; half++) {
                int row = m0 + wm + mt * 16 + g8 + half * 8;
                int hh = row >> 6, l = row & 63;
#pragma unroll
                for (int par = 0; par < 2; par++) {
                    __half hv[8];
#pragma unroll
                    for (int nt = 0; nt < 8; nt++) {
                        hv[nt] = __float2half_rn(F.a[mt][nt][half * 2 + par]);
                        float v = __half2float(hv[nt]);
                        sq[nt] += v * v;
                    }
                    int lr = l * 8 + 2 * tg + par;
                    *(uint4*)(g_Yd + ((size_t)hh * 512 + lr) * NE + mb) = *(uint4*)hv;
                }
            }
    }
#pragma unroll
    for (int nt = 0; nt < 8; nt++) {
        float v = sq[nt];
        v += __shfl_down_sync(0xffffffffu, v, 4);
        v += __shfl_down_sync(0xffffffffu, v, 8);
        v += __shfl_down_sync(0xffffffffu, v, 16);
        if (g8 == 0) atomicAdd(&csum[wn + nt * 8 + 2 * tg], v);
    }
    __syncthreads();
    if (tid < 16) {
        float s = 0.f;
#pragma unroll
        for (int j = 0; j < 8; j += 2) s += csum[tid * 8 + j];
        atomicAdd(&g_ss[p * NE + (c0 >> 3) + tid], s);
    }
}

// ---------------- scores GEMM + fused exp/softmax-numerator -----------------
__global__ __launch_bounds__(128) void scores_tc() {
    extern __shared__ __half dsm[];
    __shared__ float rsum[128];
    __half* sA = dsm;
    __half* sB = dsm + STG * ASTRH;
    const int h = blockIdx.z;
    const int m0 = blockIdx.y * 128, n0 = blockIdx.x * 128;

    const int tid = threadIdx.x, lane = tid & 31, wid = tid >> 5;
    const int g8 = lane >> 2, tg = lane & 3;
    const int wm = (wid & 1) * 64, wn = (wid >> 1) * 64;

    rsum[tid] = 0.f;

    Acc F;
    gemm_main(F, g_Y + ((size_t)h * NE + m0) * 512,
              g_Y + (((size_t)HEAD + h) * NE + n0) * 512, 512, sA, sB);

    float rk[8][2], rd[8][2];
#pragma unroll
    for (int nt = 0; nt < 8; nt++) {
        int col = n0 + wn + nt * 8 + 2 * tg;
        rk[nt][0] = rsqrtf(g_ss[NE + col]);     rk[nt][1] = rsqrtf(g_ss[NE + col + 1]);
        rd[nt][0] = rsqrtf(g_ss[2 * NE + col]); rd[nt][1] = rsqrtf(g_ss[2 * NE + col + 1]);
    }

#pragma unroll
    for (int mt = 0; mt < 4; mt++)
#pragma unroll
        for (int half = 0; half < 2; half++) {
            int row = m0 + wm + mt * 16 + g8 + half * 8;
            float rq = rsqrtf(g_ss[row]);
            float rs = 0.f;
#pragma unroll
            for (int nt = 0; nt < 8; nt++) {
                int col = n0 + wn + nt * 8 + 2 * tg;
                float e0 = __expf(F.a[mt][nt][half * 2 + 0] * rq * rk[nt][0]);
                float e1 = __expf(F.a[mt][nt][half * 2 + 1] * rq * rk[nt][1]);
                rs += e0 + e1;
                __half2 ph = make_half2(__float2half_rn(e0 * rd[nt][0]),
                                        __float2half_rn(e1 * rd[nt][1]));
                *(__half2*)(g_S + ((size_t)h * NE + row) * NE + col) = ph;
            }
            rs += __shfl_down_sync(0xffffffffu, rs, 1);
            rs += __shfl_down_sync(0xffffffffu, rs, 2);
            if (tg == 0) atomicAdd(&rsum[wm + mt * 16 + g8 + half * 8], rs);
        }
    __syncthreads();
    atomicAdd(&g_rs[(size_t)h * NE + m0 + tid], rsum[tid]);
}

// ---------------- combine GEMM, scale rows by 1/rowsum ----------------------
__global__ __launch_bounds__(128) void combine_tc(float* __restrict__ out) {
    extern __shared__ __half dsm[];
    __half* sA = dsm;
    __half* sB = dsm + STG * ASTRH;
    const int h = blockIdx.z;
    const int m0 = blockIdx.y * 128, lr0 = blockIdx.x * 128;

    Acc F;
    gemm_main(F, g_S + ((size_t)h * NE + m0) * NE,
              g_Yd + ((size_t)h * 512 + lr0) * NE, NE, sA, sB);

    const int tid = threadIdx.x, lane = tid & 31, wid = tid >> 5;
    const int g8 = lane >> 2, tg = lane & 3;
    const int wm = (wid & 1) * 64, wn = (wid >> 1) * 64;

#pragma unroll
    for (int mt = 0; mt < 4; mt++)
#pragma unroll
        for (int half = 0; half < 2; half++) {
            int row = m0 + wm + mt * 16 + g8 + half * 8;
            float inv = 1.0f / g_rs[(size_t)h * NE + row];
#pragma unroll
            for (int nt = 0; nt < 8; nt++) {
                int col = lr0 + wn + nt * 8 + 2 * tg;
                float v0 = F.a[mt][nt][half * 2 + 0] * inv;
                float v1 = F.a[mt][nt][half * 2 + 1] * inv;
                *(float2*)(out + (size_t)row * OUTC + h * 512 + col) = make_float2(v0, v1);
            }
        }
}

// ---------------------------------------------------------------------------
extern "C" void kernel_launch(void* const* d_in, const int* in_sizes, int n_in,
                              void* d_out, int out_size) {
    const float* x  = (const float*)d_in[0];
    const float* Wq = (const float*)d_in[1];
    const float* Wk = (const float*)d_in[2];
    const float* Wd = (const float*)d_in[3];
    float* out = (float*)d_out;

    cudaFuncSetAttribute(proj_tc,    cudaFuncAttributeMaxDynamicSharedMemorySize, SMEM_BYTES);
    cudaFuncSetAttribute(scores_tc,  cudaFuncAttributeMaxDynamicSharedMemorySize, SMEM_BYTES);
    cudaFuncSetAttribute(combine_tc, cudaFuncAttributeMaxDynamicSharedMemorySize, SMEM_BYTES);

    prep_all<<<NE + 768, 256>>>(x, Wq, Wk, Wd);
    proj_tc<<<dim3(NCOL / 128, HL / 128, 3), 128, SMEM_BYTES>>>();
    scores_tc<<<dim3(NE / 128, NE / 128, HEAD), 128, SMEM_BYTES>>>();
    combine_tc<<<dim3(512 / 128, NE / 128, HEAD), 128, SMEM_BYTES>>>(out);
}

// round 14
// speedup vs baseline: 1.1166x; 1.1166x over previous
#include <cuda_runtime.h>
#include <cuda_fp16.h>
#include <math.h>
#include <stdint.h>

#define NE    2048
#define FEAT  512
#define REST  8
#define HEAD  8
#define HL    512
#define NCOL  16384
#define OUTC  (HEAD*512)
#define BKH   64
#define PADH  72
#define ASTRH (128*PADH)
#define STG   3
#define SMEM_BYTES (2 * STG * ASTRH * 2)   // 110592 bytes

// ---------------- scratch ----------------------------------------------------
__device__ __half g_Y  [(size_t)2 * HEAD * NE * 512];
__device__ __half g_Yd [(size_t)HEAD * 512 * NE];
__device__ __half g_xt [(size_t)NCOL * FEAT];
__device__ __half g_W  [(size_t)3 * HL * FEAT];
__device__ __half g_S  [(size_t)HEAD * NE * NE];
__device__ float  g_ss [3 * NE];
__device__ float  g_rs [(size_t)HEAD * NE];

// ---------------- helpers ----------------------------------------------------
__device__ __forceinline__ uint32_t smem_u32(const void* p) {
    uint32_t a;
    asm("{ .reg .u64 t; cvta.to.shared.u64 t, %1; cvt.u32.u64 %0, t; }" : "=r"(a) : "l"(p));
    return a;
}
__device__ __forceinline__ void mma16(float* c, const uint32_t* a, const uint32_t* b) {
    asm volatile(
        "mma.sync.aligned.m16n8k16.row.col.f32.f16.f16.f32 "
        "{%0,%1,%2,%3}, {%4,%5,%6,%7}, {%8,%9}, {%0,%1,%2,%3};"
        : "+f"(c[0]), "+f"(c[1]), "+f"(c[2]), "+f"(c[3])
        : "r"(a[0]), "r"(a[1]), "r"(a[2]), "r"(a[3]), "r"(b[0]), "r"(b[1]));
}
__device__ __forceinline__ void ldsm4(uint32_t* r, uint32_t addr) {
    asm volatile("ldmatrix.sync.aligned.m8n8.x4.shared.b16 {%0,%1,%2,%3}, [%4];"
                 : "=r"(r[0]), "=r"(r[1]), "=r"(r[2]), "=r"(r[3]) : "r"(addr));
}
__device__ __forceinline__ void cp16(uint32_t dst, const void* src) {
    uint64_t g;
    asm("cvta.to.global.u64 %0, %1;" : "=l"(g) : "l"(src));
    asm volatile("cp.async.cg.shared.global [%0], [%1], 16;" :: "r"(dst), "l"(g));
}

__device__ __forceinline__ void ld_k(__half* S, const __half* gp, int ldk, int k0, int tid) {
#pragma unroll
    for (int i = 0; i < 8; i++) {
        int idx = tid + i * 128;
        int row = idx >> 3, ch = idx & 7;
        cp16(smem_u32(S + row * PADH + ch * 8), gp + (size_t)row * ldk + k0 + ch * 8);
    }
}

struct Acc { float a[4][8][4]; };

// ---------------- 3-stage, BK=64, fragment double-buffered mainloop ----------
__device__ __forceinline__ void gemm_main(Acc& F, const __half* A, const __half* B,
                                          int K, __half* sA, __half* sB) {
    const int tid = threadIdx.x;
    const int lane = tid & 31, wid = tid >> 5;
    const int wm = (wid & 1) * 64, wn = (wid >> 1) * 64;

    const int offA = (wm + (lane & 7) + ((lane >> 3) & 1) * 8) * PADH + ((lane >> 4) & 1) * 8;
    const int offB = (wn + (lane & 7) + ((lane >> 4) & 1) * 8) * PADH + ((lane >> 3) & 1) * 8;

    const uint32_t sA0 = smem_u32(sA), sB0 = smem_u32(sB);

#pragma unroll
    for (int mt = 0; mt < 4; mt++)
#pragma unroll
        for (int nt = 0; nt < 8; nt++)
#pragma unroll
            for (int j = 0; j < 4; j++) F.a[mt][nt][j] = 0.f;

#pragma unroll
    for (int s = 0; s < STG - 1; s++) {
        ld_k(sA + s * ASTRH, A, K, s * BKH, tid);
        ld_k(sB + s * ASTRH, B, K, s * BKH, tid);
        asm volatile("cp.async.commit_group;" ::: "memory");
    }

    const int KT = K / BKH;
    int ls = STG - 1;
    for (int kt = 0; kt < KT; kt++) {
        asm volatile("cp.async.wait_group %0;" :: "n"(STG - 2) : "memory");
        __syncthreads();
        if (kt + STG - 1 < KT) {
            ld_k(sA + ls * ASTRH, A, K, (kt + STG - 1) * BKH, tid);
            ld_k(sB + ls * ASTRH, B, K, (kt + STG - 1) * BKH, tid);
            ls = (ls + 1 == STG) ? 0 : ls + 1;
        }
        asm volatile("cp.async.commit_group;" ::: "memory");

        int buf = kt % STG;
        const uint32_t aB = sA0 + (buf * ASTRH + offA) * 2;
        const uint32_t bB = sB0 + (buf * ASTRH + offB) * 2;

        uint32_t af[2][4][4], bf[2][4][4];
#pragma unroll
        for (int mt = 0; mt < 4; mt++) ldsm4(af[0][mt], aB + (mt * 16 * PADH) * 2);
#pragma unroll
        for (int np = 0; np < 4; np++) ldsm4(bf[0][np], bB + (np * 16 * PADH) * 2);

#pragma unroll
        for (int ks = 0; ks < 4; ks++) {
            int cur = ks & 1, nxt = cur ^ 1;
            if (ks < 3) {
#pragma unroll
                for (int mt = 0; mt < 4; mt++)
                    ldsm4(af[nxt][mt], aB + (mt * 16 * PADH + 16 * (ks + 1)) * 2);
#pragma unroll
                for (int np = 0; np < 4; np++)
                    ldsm4(bf[nxt][np], bB + (np * 16 * PADH + 16 * (ks + 1)) * 2);
            }
#pragma unroll
            for (int mt = 0; mt < 4; mt++)
#pragma unroll
                for (int np = 0; np < 4; np++) {
                    mma16(F.a[mt][2 * np + 0], af[cur][mt], &bf[cur][np][0]);
                    mma16(F.a[mt][2 * np + 1], af[cur][mt], &bf[cur][np][2]);
                }
        }
    }
    __syncthreads();
}

// ---------------- fused prep: transpose x + round W + zero accumulators ------
__global__ __launch_bounds__(256) void prep_all(const float* __restrict__ x,
                                                const float* __restrict__ Wq,
                                                const float* __restrict__ Wk,
                                                const float* __restrict__ Wd) {
    int b = blockIdx.x;
    if (b < NE) {
        __shared__ float s[512 * 9];
        const int n = b, tid = threadIdx.x;
        const float* src = x + (size_t)n * 4096;
#pragma unroll
        for (int i = 0; i < 4; i++) {
            int v = (tid + i * 256) * 4;
            float4 t = *(const float4*)(src + v);
            int f = v >> 3, rr = v & 7;
            s[f * 9 + rr + 0] = t.x; s[f * 9 + rr + 1] = t.y;
            s[f * 9 + rr + 2] = t.z; s[f * 9 + rr + 3] = t.w;
        }
        __syncthreads();
#pragma unroll
        for (int rr = 0; rr < 8; rr++) {
            int f = threadIdx.x * 2;
            __half2 h = make_half2(__float2half_rn(s[f * 9 + rr]),
                                   __float2half_rn(s[(f + 1) * 9 + rr]));
            *(__half2*)(g_xt + ((size_t)n * 8 + rr) * 512 + f) = h;
        }
    } else if (b < NE + 768) {
        int bb = b - NE;
        int idx = (bb * 256 + threadIdx.x) * 4;
        int p = idx >> 18, off = idx & 262143;
        const float* W = (p == 0) ? Wq : (p == 1) ? Wk : Wd;
        float4 t = *(const float4*)(W + off);
        *(__half2*)(g_W + idx)     = make_half2(__float2half_rn(t.x), __float2half_rn(t.y));
        *(__half2*)(g_W + idx + 2) = make_half2(__float2half_rn(t.z), __float2half_rn(t.w));
        int i = bb * 256 + threadIdx.x;
        if (i < 3 * NE) g_ss[i] = 0.f;
        if (i < HEAD * NE) g_rs[i] = 0.f;
    }
}

// ---------------- projection GEMM + fused sum-of-squares --------------------
__global__ __launch_bounds__(128) void proj_tc() {
    extern __shared__ __half dsm[];
    __shared__ float csum[128];
    __half* sA = dsm;
    __half* sB = dsm + STG * ASTRH;
    const int p = blockIdx.z;
    const int m0 = blockIdx.y * 128, c0 = blockIdx.x * 128;

    const int tid = threadIdx.x, lane = tid & 31, wid = tid >> 5;
    const int g8 = lane >> 2, tg = lane & 3;
    const int wm = (wid & 1) * 64, wn = (wid >> 1) * 64;

    csum[tid] = 0.f;

    Acc F;
    gemm_main(F, g_W + (size_t)p * HL * FEAT + (size_t)m0 * FEAT,
              g_xt + (size_t)c0 * FEAT, FEAT, sA, sB);

    float sq[8];
#pragma unroll
    for (int nt = 0; nt < 8; nt++) sq[nt] = 0.f;

    if (p < 2) {
        __half* base = g_Y + (size_t)p * HEAD * NE * 512;
#pragma unroll
        for (int mt = 0; mt < 4; mt++)
#pragma unroll
            for (int half = 0; half < 2; half++) {
                int row = m0 + wm + mt * 16 + g8 + half * 8;
                int hh = row >> 6, l = row & 63;
#pragma unroll
                for (int nt = 0; nt < 8; nt++) {
                    int col = c0 + wn + nt * 8 + 2 * tg;
                    int n = col >> 3, r = col & 7;
                    __half h0 = __float2half_rn(F.a[mt][nt][half * 2 + 0]);
                    __half h1 = __float2half_rn(F.a[mt][nt][half * 2 + 1]);
                    float v0 = __half2float(h0), v1 = __half2float(h1);
                    *(__half2*)(base + ((size_t)hh * NE + n) * 512 + l * 8 + r) = make_half2(h0, h1);
                    sq[nt] += v0 * v0 + v1 * v1;
                }
            }
    } else {
        int mb = (c0 >> 3) + (wn >> 3);
#pragma unroll
        for (int mt = 0; mt < 4; mt++)
#pragma unroll
            for (int half = 0; half < 2; half++) {
                int row = m0 + wm + mt * 16 + g8 + half * 8;
                int hh = row >> 6, l = row & 63;
#pragma unroll
                for (int par = 0; par < 2; par++) {
                    __half hv[8];
#pragma unroll
                    for (int nt = 0; nt < 8; nt++) {
                        hv[nt] = __float2half_rn(F.a[mt][nt][half * 2 + par]);
                        float v = __half2float(hv[nt]);
                        sq[nt] += v * v;
                    }
                    int lr = l * 8 + 2 * tg + par;
                    *(uint4*)(g_Yd + ((size_t)hh * 512 + lr) * NE + mb) = *(uint4*)hv;
                }
            }
    }
#pragma unroll
    for (int nt = 0; nt < 8; nt++) {
        float v = sq[nt];
        v += __shfl_down_sync(0xffffffffu, v, 4);
        v += __shfl_down_sync(0xffffffffu, v, 8);
        v += __shfl_down_sync(0xffffffffu, v, 16);
        if (g8 == 0) atomicAdd(&csum[wn + nt * 8 + 2 * tg], v);
    }
    __syncthreads();
    if (tid < 16) {
        float s = 0.f;
#pragma unroll
        for (int j = 0; j < 8; j += 2) s += csum[tid * 8 + j];
        atomicAdd(&g_ss[p * NE + (c0 >> 3) + tid], s);
    }
}

// ---------------- scores GEMM + fused exp/softmax-numerator -----------------
__global__ __launch_bounds__(128) void scores_tc() {
    extern __shared__ __half dsm[];
    __shared__ float rsum[128];
    __half* sA = dsm;
    __half* sB = dsm + STG * ASTRH;
    const int h = blockIdx.z;
    const int m0 = blockIdx.y * 128, n0 = blockIdx.x * 128;

    const int tid = threadIdx.x, lane = tid & 31, wid = tid >> 5;
    const int g8 = lane >> 2, tg = lane & 3;
    const int wm = (wid & 1) * 64, wn = (wid >> 1) * 64;

    rsum[tid] = 0.f;

    Acc F;
    gemm_main(F, g_Y + ((size_t)h * NE + m0) * 512,
              g_Y + (((size_t)HEAD + h) * NE + n0) * 512, 512, sA, sB);

    float rk[8][2], rd[8][2];
#pragma unroll
    for (int nt = 0; nt < 8; nt++) {
        int col = n0 + wn + nt * 8 + 2 * tg;
        rk[nt][0] = rsqrtf(g_ss[NE + col]);     rk[nt][1] = rsqrtf(g_ss[NE + col + 1]);
        rd[nt][0] = rsqrtf(g_ss[2 * NE + col]); rd[nt][1] = rsqrtf(g_ss[2 * NE + col + 1]);
    }

#pragma unroll
    for (int mt = 0; mt < 4; mt++)
#pragma unroll
        for (int half = 0; half < 2; half++) {
            int row = m0 + wm + mt * 16 + g8 + half * 8;
            float rq = rsqrtf(g_ss[row]);
            float rs = 0.f;
#pragma unroll
            for (int nt = 0; nt < 8; nt++) {
                int col = n0 + wn + nt * 8 + 2 * tg;
                float e0 = __expf(F.a[mt][nt][half * 2 + 0] * rq * rk[nt][0]);
                float e1 = __expf(F.a[mt][nt][half * 2 + 1] * rq * rk[nt][1]);
                rs += e0 + e1;
                __half2 ph = make_half2(__float2half_rn(e0 * rd[nt][0]),
                                        __float2half_rn(e1 * rd[nt][1]));
                *(__half2*)(g_S + ((size_t)h * NE + row) * NE + col) = ph;
            }
            rs += __shfl_down_sync(0xffffffffu, rs, 1);
            rs += __shfl_down_sync(0xffffffffu, rs, 2);
            if (tg == 0) atomicAdd(&rsum[wm + mt * 16 + g8 + half * 8], rs);
        }
    __syncthreads();
    atomicAdd(&g_rs[(size_t)h * NE + m0 + tid], rsum[tid]);
}

// ---------------- combine GEMM, scale rows by 1/rowsum ----------------------
__global__ __launch_bounds__(128) void combine_tc(float* __restrict__ out) {
    extern __shared__ __half dsm[];
    __half* sA = dsm;
    __half* sB = dsm + STG * ASTRH;
    const int h = blockIdx.z;
    const int m0 = blockIdx.y * 128, lr0 = blockIdx.x * 128;

    Acc F;
    gemm_main(F, g_S + ((size_t)h * NE + m0) * NE,
              g_Yd + ((size_t)h * 512 + lr0) * NE, NE, sA, sB);

    const int tid = threadIdx.x, lane = tid & 31, wid = tid >> 5;
    const int g8 = lane >> 2, tg = lane & 3;
    const int wm = (wid & 1) * 64, wn = (wid >> 1) * 64;

#pragma unroll
    for (int mt = 0; mt < 4; mt++)
#pragma unroll
        for (int half = 0; half < 2; half++) {
            int row = m0 + wm + mt * 16 + g8 + half * 8;
            float inv = 1.0f / g_rs[(size_t)h * NE + row];
#pragma unroll
            for (int nt = 0; nt < 8; nt++) {
                int col = lr0 + wn + nt * 8 + 2 * tg;
                float v0 = F.a[mt][nt][half * 2 + 0] * inv;
                float v1 = F.a[mt][nt][half * 2 + 1] * inv;
                *(float2*)(out + (size_t)row * OUTC + h * 512 + col) = make_float2(v0, v1);
            }
        }
}

// ---------------------------------------------------------------------------
extern "C" void kernel_launch(void* const* d_in, const int* in_sizes, int n_in,
                              void* d_out, int out_size) {
    const float* x  = (const float*)d_in[0];
    const float* Wq = (const float*)d_in[1];
    const float* Wk = (const float*)d_in[2];
    const float* Wd = (const float*)d_in[3];
    float* out = (float*)d_out;

    cudaFuncSetAttribute(proj_tc,    cudaFuncAttributeMaxDynamicSharedMemorySize, SMEM_BYTES);
    cudaFuncSetAttribute(scores_tc,  cudaFuncAttributeMaxDynamicSharedMemorySize, SMEM_BYTES);
    cudaFuncSetAttribute(combine_tc, cudaFuncAttributeMaxDynamicSharedMemorySize, SMEM_BYTES);

    prep_all<<<NE + 768, 256>>>(x, Wq, Wk, Wd);
    proj_tc<<<dim3(NCOL / 128, HL / 128, 3), 128, SMEM_BYTES>>>();
    scores_tc<<<dim3(NE / 128, NE / 128, HEAD), 128, SMEM_BYTES>>>();
    combine_tc<<<dim3(512 / 128, NE / 128, HEAD), 128, SMEM_BYTES>>>(out);
}

// round 15
// speedup vs baseline: 1.1408x; 1.0217x over previous
#include <cuda_runtime.h>
#include <cuda_fp16.h>
#include <math.h>
#include <stdint.h>

#define NE    2048
#define FEAT  512
#define REST  8
#define HEAD  8
#define HL    512
#define NCOL  16384
#define OUTC  (HEAD*512)
#define BKH   64
#define PADH  72
#define ASTRH (128*PADH)
#define STG   3
#define SMEM_BYTES (2 * STG * ASTRH * 2)   // 110592 bytes
#define SPAD  136                          // staging row stride (halves)

// ---------------- scratch ----------------------------------------------------
__device__ __half g_Y  [(size_t)2 * HEAD * NE * 512];
__device__ __half g_Yd [(size_t)HEAD * 512 * NE];
__device__ __half g_xt [(size_t)NCOL * FEAT];
__device__ __half g_W  [(size_t)3 * HL * FEAT];
__device__ __half g_S  [(size_t)HEAD * NE * NE];
__device__ float  g_ss [3 * NE];
__device__ float  g_rs [(size_t)HEAD * NE];

// ---------------- helpers ----------------------------------------------------
__device__ __forceinline__ uint32_t smem_u32(const void* p) {
    uint32_t a;
    asm("{ .reg .u64 t; cvta.to.shared.u64 t, %1; cvt.u32.u64 %0, t; }" : "=r"(a) : "l"(p));
    return a;
}
__device__ __forceinline__ void mma16(float* c, const uint32_t* a, const uint32_t* b) {
    asm volatile(
        "mma.sync.aligned.m16n8k16.row.col.f32.f16.f16.f32 "
        "{%0,%1,%2,%3}, {%4,%5,%6,%7}, {%8,%9}, {%0,%1,%2,%3};"
        : "+f"(c[0]), "+f"(c[1]), "+f"(c[2]), "+f"(c[3])
        : "r"(a[0]), "r"(a[1]), "r"(a[2]), "r"(a[3]), "r"(b[0]), "r"(b[1]));
}
__device__ __forceinline__ void ldsm4(uint32_t* r, uint32_t addr) {
    asm volatile("ldmatrix.sync.aligned.m8n8.x4.shared.b16 {%0,%1,%2,%3}, [%4];"
                 : "=r"(r[0]), "=r"(r[1]), "=r"(r[2]), "=r"(r[3]) : "r"(addr));
}
__device__ __forceinline__ void cp16(uint32_t dst, const void* src) {
    uint64_t g;
    asm("cvta.to.global.u64 %0, %1;" : "=l"(g) : "l"(src));
    asm volatile("cp.async.cg.shared.global [%0], [%1], 16;" :: "r"(dst), "l"(g));
}

__device__ __forceinline__ void ld_k(__half* S, const __half* gp, int ldk, int k0, int tid) {
#pragma unroll
    for (int i = 0; i < 8; i++) {
        int idx = tid + i * 128;
        int row = idx >> 3, ch = idx & 7;
        cp16(smem_u32(S + row * PADH + ch * 8), gp + (size_t)row * ldk + k0 + ch * 8);
    }
}

struct Acc { float a[4][8][4]; };

// ---------------- 3-stage, BK=64, fragment double-buffered mainloop ----------
__device__ __forceinline__ void gemm_main(Acc& F, const __half* A, const __half* B,
                                          int K, __half* sA, __half* sB) {
    const int tid = threadIdx.x;
    const int lane = tid & 31, wid = tid >> 5;
    const int wm = (wid & 1) * 64, wn = (wid >> 1) * 64;

    const int offA = (wm + (lane & 7) + ((lane >> 3) & 1) * 8) * PADH + ((lane >> 4) & 1) * 8;
    const int offB = (wn + (lane & 7) + ((lane >> 4) & 1) * 8) * PADH + ((lane >> 3) & 1) * 8;

    const uint32_t sA0 = smem_u32(sA), sB0 = smem_u32(sB);

#pragma unroll
    for (int mt = 0; mt < 4; mt++)
#pragma unroll
        for (int nt = 0; nt < 8; nt++)
#pragma unroll
            for (int j = 0; j < 4; j++) F.a[mt][nt][j] = 0.f;

#pragma unroll
    for (int s = 0; s < STG - 1; s++) {
        ld_k(sA + s * ASTRH, A, K, s * BKH, tid);
        ld_k(sB + s * ASTRH, B, K, s * BKH, tid);
        asm volatile("cp.async.commit_group;" ::: "memory");
    }

    const int KT = K / BKH;
    int ls = STG - 1;
    for (int kt = 0; kt < KT; kt++) {
        asm volatile("cp.async.wait_group %0;" :: "n"(STG - 2) : "memory");
        __syncthreads();
        if (kt + STG - 1 < KT) {
            ld_k(sA + ls * ASTRH, A, K, (kt + STG - 1) * BKH, tid);
            ld_k(sB + ls * ASTRH, B, K, (kt + STG - 1) * BKH, tid);
            ls = (ls + 1 == STG) ? 0 : ls + 1;
        }
        asm volatile("cp.async.commit_group;" ::: "memory");

        int buf = kt % STG;
        const uint32_t aB = sA0 + (buf * ASTRH + offA) * 2;
        const uint32_t bB = sB0 + (buf * ASTRH + offB) * 2;

        uint32_t af[2][4][4], bf[2][4][4];
#pragma unroll
        for (int mt = 0; mt < 4; mt++) ldsm4(af[0][mt], aB + (mt * 16 * PADH) * 2);
#pragma unroll
        for (int np = 0; np < 4; np++) ldsm4(bf[0][np], bB + (np * 16 * PADH) * 2);

#pragma unroll
        for (int ks = 0; ks < 4; ks++) {
            int cur = ks & 1, nxt = cur ^ 1;
            if (ks < 3) {
#pragma unroll
                for (int mt = 0; mt < 4; mt++)
                    ldsm4(af[nxt][mt], aB + (mt * 16 * PADH + 16 * (ks + 1)) * 2);
#pragma unroll
                for (int np = 0; np < 4; np++)
                    ldsm4(bf[nxt][np], bB + (np * 16 * PADH + 16 * (ks + 1)) * 2);
            }
#pragma unroll
            for (int mt = 0; mt < 4; mt++)
#pragma unroll
                for (int np = 0; np < 4; np++) {
                    mma16(F.a[mt][2 * np + 0], af[cur][mt], &bf[cur][np][0]);
                    mma16(F.a[mt][2 * np + 1], af[cur][mt], &bf[cur][np][2]);
                }
        }
    }
    __syncthreads();
}

// ---------------- fused prep: transpose x + round W + zero accumulators ------
__global__ __launch_bounds__(256) void prep_all(const float* __restrict__ x,
                                                const float* __restrict__ Wq,
                                                const float* __restrict__ Wk,
                                                const float* __restrict__ Wd) {
    int b = blockIdx.x;
    if (b < NE) {
        __shared__ float s[512 * 9];
        const int n = b, tid = threadIdx.x;
        const float* src = x + (size_t)n * 4096;
#pragma unroll
        for (int i = 0; i < 4; i++) {
            int v = (tid + i * 256) * 4;
            float4 t = *(const float4*)(src + v);
            int f = v >> 3, rr = v & 7;
            s[f * 9 + rr + 0] = t.x; s[f * 9 + rr + 1] = t.y;
            s[f * 9 + rr + 2] = t.z; s[f * 9 + rr + 3] = t.w;
        }
        __syncthreads();
#pragma unroll
        for (int rr = 0; rr < 8; rr++) {
            int f = threadIdx.x * 2;
            __half2 h = make_half2(__float2half_rn(s[f * 9 + rr]),
                                   __float2half_rn(s[(f + 1) * 9 + rr]));
            *(__half2*)(g_xt + ((size_t)n * 8 + rr) * 512 + f) = h;
        }
    } else if (b < NE + 768) {
        int bb = b - NE;
        int idx = (bb * 256 + threadIdx.x) * 4;
        int p = idx >> 18, off = idx & 262143;
        const float* W = (p == 0) ? Wq : (p == 1) ? Wk : Wd;
        float4 t = *(const float4*)(W + off);
        *(__half2*)(g_W + idx)     = make_half2(__float2half_rn(t.x), __float2half_rn(t.y));
        *(__half2*)(g_W + idx + 2) = make_half2(__float2half_rn(t.z), __float2half_rn(t.w));
        int i = bb * 256 + threadIdx.x;
        if (i < 3 * NE) g_ss[i] = 0.f;
        if (i < HEAD * NE) g_rs[i] = 0.f;
    }
}

// ---------------- projection GEMM + fused sum-of-squares --------------------
__global__ __launch_bounds__(128) void proj_tc() {
    extern __shared__ __half dsm[];
    __shared__ float csum[128];
    __half* sA = dsm;
    __half* sB = dsm + STG * ASTRH;
    const int p = blockIdx.z;
    const int m0 = blockIdx.y * 128, c0 = blockIdx.x * 128;

    const int tid = threadIdx.x, lane = tid & 31, wid = tid >> 5;
    const int g8 = lane >> 2, tg = lane & 3;
    const int wm = (wid & 1) * 64, wn = (wid >> 1) * 64;

    csum[tid] = 0.f;

    Acc F;
    gemm_main(F, g_W + (size_t)p * HL * FEAT + (size_t)m0 * FEAT,
              g_xt + (size_t)c0 * FEAT, FEAT, sA, sB);

    float sq[8];
#pragma unroll
    for (int nt = 0; nt < 8; nt++) sq[nt] = 0.f;

    if (p < 2) {
        __half* base = g_Y + (size_t)p * HEAD * NE * 512;
#pragma unroll
        for (int mt = 0; mt < 4; mt++)
#pragma unroll
            for (int half = 0; half < 2; half++) {
                int row = m0 + wm + mt * 16 + g8 + half * 8;
                int hh = row >> 6, l = row & 63;
#pragma unroll
                for (int nt = 0; nt < 8; nt++) {
                    int col = c0 + wn + nt * 8 + 2 * tg;
                    int n = col >> 3, r = col & 7;
                    __half h0 = __float2half_rn(F.a[mt][nt][half * 2 + 0]);
                    __half h1 = __float2half_rn(F.a[mt][nt][half * 2 + 1]);
                    float v0 = __half2float(h0), v1 = __half2float(h1);
                    *(__half2*)(base + ((size_t)hh * NE + n) * 512 + l * 8 + r) = make_half2(h0, h1);
                    sq[nt] += v0 * v0 + v1 * v1;
                }
            }
    } else {
        // stage d tile in smem, then write 32B full-sector row chunks
        __half* sSt = dsm;
#pragma unroll
        for (int mt = 0; mt < 4; mt++)
#pragma unroll
            for (int half = 0; half < 2; half++) {
                int srow = wm + mt * 16 + g8 + half * 8;
#pragma unroll
                for (int nt = 0; nt < 8; nt++) {
                    int scol = wn + nt * 8 + 2 * tg;
                    __half h0 = __float2half_rn(F.a[mt][nt][half * 2 + 0]);
                    __half h1 = __float2half_rn(F.a[mt][nt][half * 2 + 1]);
                    float v0 = __half2float(h0), v1 = __half2float(h1);
                    sq[nt] += v0 * v0 + v1 * v1;
                    *(__half2*)(sSt + srow * SPAD + scol) = make_half2(h0, h1);
                }
            }
        __syncthreads();
        {
            int i = tid;                       // hl-row within tile
            int rowg = m0 + i, hh = rowg >> 6, l = rowg & 63;
            int mb0 = c0 >> 3;                 // 16-aligned -> 32B-aligned dst
#pragma unroll
            for (int rp = 0; rp < 4; rp++) {   // r pairs (2rp, 2rp+1)
                __half ra[16], rb[16];
#pragma unroll
                for (int m = 0; m < 16; m++) {
                    __half2 u = *(__half2*)(sSt + i * SPAD + m * 8 + 2 * rp);
                    ra[m] = u.x; rb[m] = u.y;
                }
                __half* d0 = g_Yd + ((size_t)hh * 512 + l * 8 + 2 * rp) * NE + mb0;
                __half* d1 = d0 + NE;
                *(uint4*)d0 = *(uint4*)ra;  *(uint4*)(d0 + 8) = *(uint4*)(ra + 8);
                *(uint4*)d1 = *(uint4*)rb;  *(uint4*)(d1 + 8) = *(uint4*)(rb + 8);
            }
        }
        __syncthreads();
    }
#pragma unroll
    for (int nt = 0; nt < 8; nt++) {
        float v = sq[nt];
        v += __shfl_down_sync(0xffffffffu, v, 4);
        v += __shfl_down_sync(0xffffffffu, v, 8);
        v += __shfl_down_sync(0xffffffffu, v, 16);
        if (g8 == 0) atomicAdd(&csum[wn + nt * 8 + 2 * tg], v);
    }
    __syncthreads();
    if (tid < 16) {
        float s = 0.f;
#pragma unroll
        for (int j = 0; j < 8; j += 2) s += csum[tid * 8 + j];
        atomicAdd(&g_ss[p * NE + (c0 >> 3) + tid], s);
    }
}

// ---------------- scores GEMM + fused exp, staged coalesced S writes --------
__global__ __launch_bounds__(128) void scores_tc() {
    extern __shared__ __half dsm[];
    __shared__ float rsum[128];
    __half* sA = dsm;
    __half* sB = dsm + STG * ASTRH;
    const int h = blockIdx.z;
    const int m0 = blockIdx.y * 128, n0 = blockIdx.x * 128;

    const int tid = threadIdx.x, lane = tid & 31, wid = tid >> 5;
    const int g8 = lane >> 2, tg = lane & 3;
    const int wm = (wid & 1) * 64, wn = (wid >> 1) * 64;

    rsum[tid] = 0.f;

    Acc F;
    gemm_main(F, g_Y + ((size_t)h * NE + m0) * 512,
              g_Y + (((size_t)HEAD + h) * NE + n0) * 512, 512, sA, sB);

    float rk[8][2], rd[8][2];
#pragma unroll
    for (int nt = 0; nt < 8; nt++) {
        int col = n0 + wn + nt * 8 + 2 * tg;
        rk[nt][0] = rsqrtf(g_ss[NE + col]);     rk[nt][1] = rsqrtf(g_ss[NE + col + 1]);
        rd[nt][0] = rsqrtf(g_ss[2 * NE + col]); rd[nt][1] = rsqrtf(g_ss[2 * NE + col + 1]);
    }

    __half* sSt = dsm;     // stage S tile (gemm_main ended with a barrier)
#pragma unroll
    for (int mt = 0; mt < 4; mt++)
#pragma unroll
        for (int half = 0; half < 2; half++) {
            int srow = wm + mt * 16 + g8 + half * 8;
            float rq = rsqrtf(g_ss[m0 + srow]);
            float rs = 0.f;
#pragma unroll
            for (int nt = 0; nt < 8; nt++) {
                int scol = wn + nt * 8 + 2 * tg;
                float e0 = __expf(F.a[mt][nt][half * 2 + 0] * rq * rk[nt][0]);
                float e1 = __expf(F.a[mt][nt][half * 2 + 1] * rq * rk[nt][1]);
                rs += e0 + e1;
                __half2 ph = make_half2(__float2half_rn(e0 * rd[nt][0]),
                                        __float2half_rn(e1 * rd[nt][1]));
                *(__half2*)(sSt + srow * SPAD + scol) = ph;
            }
            rs += __shfl_down_sync(0xffffffffu, rs, 1);
            rs += __shfl_down_sync(0xffffffffu, rs, 2);
            if (tg == 0) atomicAdd(&rsum[wm + mt * 16 + g8 + half * 8], rs);
        }
    __syncthreads();

    // coalesced writeout: each warp writes 256B contiguous per row
    {
        const size_t rowg = (size_t)h * NE + m0;
#pragma unroll
        for (int it = 0; it < 32; it++) {
            int row = it * 4 + wid;
            uint2 v = *(uint2*)(sSt + row * SPAD + lane * 4);
            *(uint2*)(g_S + (rowg + row) * NE + n0 + lane * 4) = v;
        }
    }
    atomicAdd(&g_rs[(size_t)h * NE + m0 + tid], rsum[tid]);
}

// ---------------- combine GEMM, scale rows by 1/rowsum ----------------------
__global__ __launch_bounds__(128) void combine_tc(float* __restrict__ out) {
    extern __shared__ __half dsm[];
    __half* sA = dsm;
    __half* sB = dsm + STG * ASTRH;
    const int h = blockIdx.z;
    const int m0 = blockIdx.y * 128, lr0 = blockIdx.x * 128;

    Acc F;
    gemm_main(F, g_S + ((size_t)h * NE + m0) * NE,
              g_Yd + ((size_t)h * 512 + lr0) * NE, NE, sA, sB);

    const int tid = threadIdx.x, lane = tid & 31, wid = tid >> 5;
    const int g8 = lane >> 2, tg = lane & 3;
    const int wm = (wid & 1) * 64, wn = (wid >> 1) * 64;

#pragma unroll
    for (int mt = 0; mt < 4; mt++)
#pragma unroll
        for (int half = 0; half < 2; half++) {
            int row = m0 + wm + mt * 16 + g8 + half * 8;
            float inv = 1.0f / g_rs[(size_t)h * NE + row];
#pragma unroll
            for (int nt = 0; nt < 8; nt++) {
                int col = lr0 + wn + nt * 8 + 2 * tg;
                float v0 = F.a[mt][nt][half * 2 + 0] * inv;
                float v1 = F.a[mt][nt][half * 2 + 1] * inv;
                *(float2*)(out + (size_t)row * OUTC + h * 512 + col) = make_float2(v0, v1);
            }
        }
}

// ---------------------------------------------------------------------------
extern "C" void kernel_launch(void* const* d_in, const int* in_sizes, int n_in,
                              void* d_out, int out_size) {
    const float* x  = (const float*)d_in[0];
    const float* Wq = (const float*)d_in[1];
    const float* Wk = (const float*)d_in[2];
    const float* Wd = (const float*)d_in[3];
    float* out = (float*)d_out;

    cudaFuncSetAttribute(proj_tc,    cudaFuncAttributeMaxDynamicSharedMemorySize, SMEM_BYTES);
    cudaFuncSetAttribute(scores_tc,  cudaFuncAttributeMaxDynamicSharedMemorySize, SMEM_BYTES);
    cudaFuncSetAttribute(combine_tc, cudaFuncAttributeMaxDynamicSharedMemorySize, SMEM_BYTES);

    prep_all<<<NE + 768, 256>>>(x, Wq, Wk, Wd);
    proj_tc<<<dim3(NCOL / 128, HL / 128, 3), 128, SMEM_BYTES>>>();
    scores_tc<<<dim3(NE / 128, NE / 128, HEAD), 128, SMEM_BYTES>>>();
    combine_tc<<<dim3(512 / 128, NE / 128, HEAD), 128, SMEM_BYTES>>>(out);
}

// round 16
// speedup vs baseline: 1.1645x; 1.0208x over previous
#include <cuda_runtime.h>
#include <cuda_fp16.h>
#include <math.h>
#include <stdint.h>

#define NE    2048
#define FEAT  512
#define REST  8
#define HEAD  8
#define HL    512
#define NCOL  16384
#define OUTC  (HEAD*512)
#define BKH   64
#define PADH  72
#define ASTRH (128*PADH)
#define STG   3
#define SMEM_BYTES (2 * STG * ASTRH * 2)   // 110592 bytes
#define SPAD  136
#define NTILE 4096                          // 1536 proj + 2048 scores + 512 combine

// ---------------- scratch ----------------------------------------------------
__device__ __half g_Y  [(size_t)2 * HEAD * NE * 512];
__device__ __half g_Yd [(size_t)HEAD * 512 * NE];
__device__ __half g_xt [(size_t)NCOL * FEAT];
__device__ __half g_W  [(size_t)3 * HL * FEAT];
__device__ __half g_S  [(size_t)HEAD * NE * NE];
__device__ float  g_ss [3 * NE];
__device__ float  g_rs [(size_t)HEAD * NE];
__device__ int    g_ec [16];     // proj completion per electron-128-block (target 96)
__device__ int    g_hc [8];      // scores completion per head (target 256)
__device__ int    g_ticket;

// ---------------- helpers ----------------------------------------------------
__device__ __forceinline__ uint32_t smem_u32(const void* p) {
    uint32_t a;
    asm("{ .reg .u64 t; cvta.to.shared.u64 t, %1; cvt.u32.u64 %0, t; }" : "=r"(a) : "l"(p));
    return a;
}
__device__ __forceinline__ void mma16(float* c, const uint32_t* a, const uint32_t* b) {
    asm volatile(
        "mma.sync.aligned.m16n8k16.row.col.f32.f16.f16.f32 "
        "{%0,%1,%2,%3}, {%4,%5,%6,%7}, {%8,%9}, {%0,%1,%2,%3};"
        : "+f"(c[0]), "+f"(c[1]), "+f"(c[2]), "+f"(c[3])
        : "r"(a[0]), "r"(a[1]), "r"(a[2]), "r"(a[3]), "r"(b[0]), "r"(b[1]));
}
__device__ __forceinline__ void ldsm4(uint32_t* r, uint32_t addr) {
    asm volatile("ldmatrix.sync.aligned.m8n8.x4.shared.b16 {%0,%1,%2,%3}, [%4];"
                 : "=r"(r[0]), "=r"(r[1]), "=r"(r[2]), "=r"(r[3]) : "r"(addr));
}
__device__ __forceinline__ void cp16(uint32_t dst, const void* src) {
    uint64_t g;
    asm("cvta.to.global.u64 %0, %1;" : "=l"(g) : "l"(src));
    asm volatile("cp.async.cg.shared.global [%0], [%1], 16;" :: "r"(dst), "l"(g));
}
__device__ __forceinline__ void wait_cnt(int* p, int target) {
    if (threadIdx.x == 0) {
        while (*(volatile int*)p < target) __nanosleep(128);
    }
    __syncthreads();
}

__device__ __forceinline__ void ld_k(__half* S, const __half* gp, int ldk, int k0, int tid) {
#pragma unroll
    for (int i = 0; i < 8; i++) {
        int idx = tid + i * 128;
        int row = idx >> 3, ch = idx & 7;
        cp16(smem_u32(S + row * PADH + ch * 8), gp + (size_t)row * ldk + k0 + ch * 8);
    }
}

struct Acc { float a[4][8][4]; };

// ---------------- 3-stage, BK=64, fragment double-buffered mainloop ----------
__device__ __forceinline__ void gemm_main(Acc& F, const __half* A, const __half* B,
                                          int K, __half* sA, __half* sB) {
    const int tid = threadIdx.x;
    const int lane = tid & 31, wid = tid >> 5;
    const int wm = (wid & 1) * 64, wn = (wid >> 1) * 64;

    const int offA = (wm + (lane & 7) + ((lane >> 3) & 1) * 8) * PADH + ((lane >> 4) & 1) * 8;
    const int offB = (wn + (lane & 7) + ((lane >> 4) & 1) * 8) * PADH + ((lane >> 3) & 1) * 8;

    const uint32_t sA0 = smem_u32(sA), sB0 = smem_u32(sB);

#pragma unroll
    for (int mt = 0; mt < 4; mt++)
#pragma unroll
        for (int nt = 0; nt < 8; nt++)
#pragma unroll
            for (int j = 0; j < 4; j++) F.a[mt][nt][j] = 0.f;

#pragma unroll
    for (int s = 0; s < STG - 1; s++) {
        ld_k(sA + s * ASTRH, A, K, s * BKH, tid);
        ld_k(sB + s * ASTRH, B, K, s * BKH, tid);
        asm volatile("cp.async.commit_group;" ::: "memory");
    }

    const int KT = K / BKH;
    int ls = STG - 1;
    for (int kt = 0; kt < KT; kt++) {
        asm volatile("cp.async.wait_group %0;" :: "n"(STG - 2) : "memory");
        __syncthreads();
        if (kt + STG - 1 < KT) {
            ld_k(sA + ls * ASTRH, A, K, (kt + STG - 1) * BKH, tid);
            ld_k(sB + ls * ASTRH, B, K, (kt + STG - 1) * BKH, tid);
            ls = (ls + 1 == STG) ? 0 : ls + 1;
        }
        asm volatile("cp.async.commit_group;" ::: "memory");

        int buf = kt % STG;
        const uint32_t aB = sA0 + (buf * ASTRH + offA) * 2;
        const uint32_t bB = sB0 + (buf * ASTRH + offB) * 2;

        uint32_t af[2][4][4], bf[2][4][4];
#pragma unroll
        for (int mt = 0; mt < 4; mt++) ldsm4(af[0][mt], aB + (mt * 16 * PADH) * 2);
#pragma unroll
        for (int np = 0; np < 4; np++) ldsm4(bf[0][np], bB + (np * 16 * PADH) * 2);

#pragma unroll
        for (int ks = 0; ks < 4; ks++) {
            int cur = ks & 1, nxt = cur ^ 1;
            if (ks < 3) {
#pragma unroll
                for (int mt = 0; mt < 4; mt++)
                    ldsm4(af[nxt][mt], aB + (mt * 16 * PADH + 16 * (ks + 1)) * 2);
#pragma unroll
                for (int np = 0; np < 4; np++)
                    ldsm4(bf[nxt][np], bB + (np * 16 * PADH + 16 * (ks + 1)) * 2);
            }
#pragma unroll
            for (int mt = 0; mt < 4; mt++)
#pragma unroll
                for (int np = 0; np < 4; np++) {
                    mma16(F.a[mt][2 * np + 0], af[cur][mt], &bf[cur][np][0]);
                    mma16(F.a[mt][2 * np + 1], af[cur][mt], &bf[cur][np][2]);
                }
        }
    }
    __syncthreads();
}

// ---------------- fused prep: transpose x + round W + zero counters ----------
__global__ __launch_bounds__(256) void prep_all(const float* __restrict__ x,
                                                const float* __restrict__ Wq,
                                                const float* __restrict__ Wk,
                                                const float* __restrict__ Wd) {
    int b = blockIdx.x;
    if (b < NE) {
        __shared__ float s[512 * 9];
        const int n = b, tid = threadIdx.x;
        const float* src = x + (size_t)n * 4096;
#pragma unroll
        for (int i = 0; i < 4; i++) {
            int v = (tid + i * 256) * 4;
            float4 t = *(const float4*)(src + v);
            int f = v >> 3, rr = v & 7;
            s[f * 9 + rr + 0] = t.x; s[f * 9 + rr + 1] = t.y;
            s[f * 9 + rr + 2] = t.z; s[f * 9 + rr + 3] = t.w;
        }
        __syncthreads();
#pragma unroll
        for (int rr = 0; rr < 8; rr++) {
            int f = threadIdx.x * 2;
            __half2 h = make_half2(__float2half_rn(s[f * 9 + rr]),
                                   __float2half_rn(s[(f + 1) * 9 + rr]));
            *(__half2*)(g_xt + ((size_t)n * 8 + rr) * 512 + f) = h;
        }
    } else if (b < NE + 768) {
        int bb = b - NE;
        int idx = (bb * 256 + threadIdx.x) * 4;
        int p = idx >> 18, off = idx & 262143;
        const float* W = (p == 0) ? Wq : (p == 1) ? Wk : Wd;
        float4 t = *(const float4*)(W + off);
        *(__half2*)(g_W + idx)     = make_half2(__float2half_rn(t.x), __float2half_rn(t.y));
        *(__half2*)(g_W + idx + 2) = make_half2(__float2half_rn(t.z), __float2half_rn(t.w));
        int i = bb * 256 + threadIdx.x;
        if (i < 3 * NE) g_ss[i] = 0.f;
        if (i < HEAD * NE) g_rs[i] = 0.f;
        if (bb == 0) {
            if (threadIdx.x < 16) g_ec[threadIdx.x] = 0;
            if (threadIdx.x < 8)  g_hc[threadIdx.x] = 0;
            if (threadIdx.x == 0) g_ticket = 0;
        }
    }
}

// ---------------- tile bodies ------------------------------------------------
__device__ __forceinline__ void proj_tile(int e, int p, int m0, int c0,
                                          __half* sA, __half* sB, float* red) {
    const int tid = threadIdx.x, lane = tid & 31, wid = tid >> 5;
    const int g8 = lane >> 2, tg = lane & 3;
    const int wm = (wid & 1) * 64, wn = (wid >> 1) * 64;

    red[tid] = 0.f;

    Acc F;
    gemm_main(F, g_W + (size_t)p * HL * FEAT + (size_t)m0 * FEAT,
              g_xt + (size_t)c0 * FEAT, FEAT, sA, sB);

    float sq[8];
#pragma unroll
    for (int nt = 0; nt < 8; nt++) sq[nt] = 0.f;

    if (p < 2) {
        __half* base = g_Y + (size_t)p * HEAD * NE * 512;
#pragma unroll
        for (int mt = 0; mt < 4; mt++)
#pragma unroll
            for (int half = 0; half < 2; half++) {
                int row = m0 + wm + mt * 16 + g8 + half * 8;
                int hh = row >> 6, l = row & 63;
#pragma unroll
                for (int nt = 0; nt < 8; nt++) {
                    int col = c0 + wn + nt * 8 + 2 * tg;
                    int n = col >> 3, r = col & 7;
                    __half h0 = __float2half_rn(F.a[mt][nt][half * 2 + 0]);
                    __half h1 = __float2half_rn(F.a[mt][nt][half * 2 + 1]);
                    float v0 = __half2float(h0), v1 = __half2float(h1);
                    *(__half2*)(base + ((size_t)hh * NE + n) * 512 + l * 8 + r) = make_half2(h0, h1);
                    sq[nt] += v0 * v0 + v1 * v1;
                }
            }
    } else {
        __half* sSt = sA;          // reuse gemm smem for staging
#pragma unroll
        for (int mt = 0; mt < 4; mt++)
#pragma unroll
            for (int half = 0; half < 2; half++) {
                int srow = wm + mt * 16 + g8 + half * 8;
#pragma unroll
                for (int nt = 0; nt < 8; nt++) {
                    int scol = wn + nt * 8 + 2 * tg;
                    __half h0 = __float2half_rn(F.a[mt][nt][half * 2 + 0]);
                    __half h1 = __float2half_rn(F.a[mt][nt][half * 2 + 1]);
                    float v0 = __half2float(h0), v1 = __half2float(h1);
                    sq[nt] += v0 * v0 + v1 * v1;
                    *(__half2*)(sSt + srow * SPAD + scol) = make_half2(h0, h1);
                }
            }
        __syncthreads();
        {
            int i = tid;
            int rowg = m0 + i, hh = rowg >> 6, l = rowg & 63;
            int mb0 = c0 >> 3;
#pragma unroll
            for (int rp = 0; rp < 4; rp++) {
                __half ra[16], rb[16];
#pragma unroll
                for (int m = 0; m < 16; m++) {
                    __half2 u = *(__half2*)(sSt + i * SPAD + m * 8 + 2 * rp);
                    ra[m] = u.x; rb[m] = u.y;
                }
                __half* d0 = g_Yd + ((size_t)hh * 512 + l * 8 + 2 * rp) * NE + mb0;
                __half* d1 = d0 + NE;
                *(uint4*)d0 = *(uint4*)ra;  *(uint4*)(d0 + 8) = *(uint4*)(ra + 8);
                *(uint4*)d1 = *(uint4*)rb;  *(uint4*)(d1 + 8) = *(uint4*)(rb + 8);
            }
        }
        __syncthreads();
    }
#pragma unroll
    for (int nt = 0; nt < 8; nt++) {
        float v = sq[nt];
        v += __shfl_down_sync(0xffffffffu, v, 4);
        v += __shfl_down_sync(0xffffffffu, v, 8);
        v += __shfl_down_sync(0xffffffffu, v, 16);
        if (g8 == 0) atomicAdd(&red[wn + nt * 8 + 2 * tg], v);
    }
    __syncthreads();
    if (tid < 16) {
        float s = 0.f;
#pragma unroll
        for (int j = 0; j < 8; j += 2) s += red[tid * 8 + j];
        atomicAdd(&g_ss[p * NE + (c0 >> 3) + tid], s);
    }
    __syncthreads();
    if (tid == 0) {
        __threadfence();
        atomicAdd(&g_ec[e], 1);
    }
}

__device__ __forceinline__ void scores_tile(int h, int m0, int n0,
                                            __half* sA, __half* sB, float* red) {
    const int tid = threadIdx.x, lane = tid & 31, wid = tid >> 5;
    const int g8 = lane >> 2, tg = lane & 3;
    const int wm = (wid & 1) * 64, wn = (wid >> 1) * 64;

    wait_cnt(&g_ec[m0 >> 7], 96);
    wait_cnt(&g_ec[n0 >> 7], 96);

    red[tid] = 0.f;

    Acc F;
    gemm_main(F, g_Y + ((size_t)h * NE + m0) * 512,
              g_Y + (((size_t)HEAD + h) * NE + n0) * 512, 512, sA, sB);

    float rk[8][2], rd[8][2];
#pragma unroll
    for (int nt = 0; nt < 8; nt++) {
        int col = n0 + wn + nt * 8 + 2 * tg;
        rk[nt][0] = rsqrtf(g_ss[NE + col]);     rk[nt][1] = rsqrtf(g_ss[NE + col + 1]);
        rd[nt][0] = rsqrtf(g_ss[2 * NE + col]); rd[nt][1] = rsqrtf(g_ss[2 * NE + col + 1]);
    }

    __half* sSt = sA;
#pragma unroll
    for (int mt = 0; mt < 4; mt++)
#pragma unroll
        for (int half = 0; half < 2; half++) {
            int srow = wm + mt * 16 + g8 + half * 8;
            float rq = rsqrtf(g_ss[m0 + srow]);
            float rs = 0.f;
#pragma unroll
            for (int nt = 0; nt < 8; nt++) {
                int scol = wn + nt * 8 + 2 * tg;
                float e0 = __expf(F.a[mt][nt][half * 2 + 0] * rq * rk[nt][0]);
                float e1 = __expf(F.a[mt][nt][half * 2 + 1] * rq * rk[nt][1]);
                rs += e0 + e1;
                __half2 ph = make_half2(__float2half_rn(e0 * rd[nt][0]),
                                        __float2half_rn(e1 * rd[nt][1]));
                *(__half2*)(sSt + srow * SPAD + scol) = ph;
            }
            rs += __shfl_down_sync(0xffffffffu, rs, 1);
            rs += __shfl_down_sync(0xffffffffu, rs, 2);
            if (tg == 0) atomicAdd(&red[wm + mt * 16 + g8 + half * 8], rs);
        }
    __syncthreads();

    {
        const size_t rowg = (size_t)h * NE + m0;
#pragma unroll
        for (int it = 0; it < 32; it++) {
            int row = it * 4 + wid;
            uint2 v = *(uint2*)(sSt + row * SPAD + lane * 4);
            *(uint2*)(g_S + (rowg + row) * NE + n0 + lane * 4) = v;
        }
    }
    atomicAdd(&g_rs[(size_t)h * NE + m0 + tid], red[tid]);
    __syncthreads();
    if (tid == 0) {
        __threadfence();
        atomicAdd(&g_hc[h], 1);
    }
}

__device__ __forceinline__ void combine_tile(int h, int m0, int lr0,
                                             __half* sA, __half* sB, float* out) {
    const int tid = threadIdx.x, lane = tid & 31, wid = tid >> 5;
    const int g8 = lane >> 2, tg = lane & 3;
    const int wm = (wid & 1) * 64, wn = (wid >> 1) * 64;

    wait_cnt(&g_hc[h], 256);

    Acc F;
    gemm_main(F, g_S + ((size_t)h * NE + m0) * NE,
              g_Yd + ((size_t)h * 512 + lr0) * NE, NE, sA, sB);

#pragma unroll
    for (int mt = 0; mt < 4; mt++)
#pragma unroll
        for (int half = 0; half < 2; half++) {
            int row = m0 + wm + mt * 16 + g8 + half * 8;
            float inv = 1.0f / g_rs[(size_t)h * NE + row];
#pragma unroll
            for (int nt = 0; nt < 8; nt++) {
                int col = lr0 + wn + nt * 8 + 2 * tg;
                float v0 = F.a[mt][nt][half * 2 + 0] * inv;
                float v1 = F.a[mt][nt][half * 2 + 1] * inv;
                *(float2*)(out + (size_t)row * OUTC + h * 512 + col) = make_float2(v0, v1);
            }
        }
}

// ---------------- persistent main kernel -------------------------------------
__global__ __launch_bounds__(128) void main_tc(float* __restrict__ out) {
    extern __shared__ __half dsm[];
    __shared__ int s_tile;
    __shared__ float red[128];
    __half* sA = dsm;
    __half* sB = dsm + STG * ASTRH;
    const int tid = threadIdx.x;

    for (;;) {
        __syncthreads();
        if (tid == 0) s_tile = atomicAdd(&g_ticket, 1);
        __syncthreads();
        int idx = s_tile;
        if (idx >= NTILE) return;

        if (idx < 1536) {
            int e = idx / 96, r = idx % 96;
            int p = r >> 5, r2 = r & 31;
            int m0 = (r2 >> 3) * 128;
            int c0 = (e * 8 + (r2 & 7)) * 128;
            proj_tile(e, p, m0, c0, sA, sB, red);
        } else if (idx < 3584) {
            int s = idx - 1536;
            int h = s >> 8, i = (s >> 4) & 15, j = s & 15;
            scores_tile(h, i * 128, j * 128, sA, sB, red);
        } else {
            int c = idx - 3584;
            int h = c >> 6, r = c & 63;
            combine_tile(h, (r >> 2) * 128, (r & 3) * 128, sA, sB, out);
        }
    }
}

// ---------------------------------------------------------------------------
extern "C" void kernel_launch(void* const* d_in, const int* in_sizes, int n_in,
                              void* d_out, int out_size) {
    const float* x  = (const float*)d_in[0];
    const float* Wq = (const float*)d_in[1];
    const float* Wk = (const float*)d_in[2];
    const float* Wd = (const float*)d_in[3];
    float* out = (float*)d_out;

    cudaFuncSetAttribute(main_tc, cudaFuncAttributeMaxDynamicSharedMemorySize, SMEM_BYTES);

    prep_all<<<NE + 768, 256>>>(x, Wq, Wk, Wd);
    main_tc<<<296, 128, SMEM_BYTES>>>(out);
}